// round 1
// baseline (speedup 1.0000x reference)
#include <cuda_runtime.h>
#include <cuda_bf16.h>

// FastMMGCN: LightGCN-style 3-layer propagation over a bipartite user-item graph.
//
// Inputs (metadata order):
//   d_in[0] user_table  f32 [100000, 64]
//   d_in[1] item_table  f32 [50000, 64]
//   d_in[2] user_idx    i32 [2000000]
//   d_in[3] item_idx    i32 [2000000]
//   d_in[4] num_layers  i32 scalar (device-resident; read on device only)
// Output: f32 [150000, 64] = concat(acc_u, acc_i) / (num_layers+1)

#define NUSERS 100000
#define NITEMS 50000
#define MAXE   2000000
#define EMB_D  64
#define MAX_LAYERS 4

#define NU4 (NUSERS * EMB_D / 4)   // 1,600,000 float4
#define NI4 (NITEMS * EMB_D / 4)   //   800,000 float4
#define NT4 (NU4 + NI4)            // 2,400,000 float4

// Scratch (static device globals; allocation inside kernel_launch is forbidden)
__device__ int   g_deg_u[NUSERS];
__device__ int   g_deg_i[NITEMS];
__device__ float g_norm[MAXE];
__device__ float g_ua[NUSERS * EMB_D];   // ping
__device__ float g_ub[NUSERS * EMB_D];   // pong
__device__ float g_ia[NITEMS * EMB_D];
__device__ float g_ib[NITEMS * EMB_D];

__device__ __forceinline__ void red_add_v4(float* p, float4 v) {
    // No-return vector reduction: 1 L2 op per 16B instead of 4 scalar atomics.
    asm volatile("red.global.add.v4.f32 [%0], {%1,%2,%3,%4};"
                 :: "l"(p), "f"(v.x), "f"(v.y), "f"(v.z), "f"(v.w)
                 : "memory");
}

// ---------------------------------------------------------------------------
__global__ void __launch_bounds__(256) zero_deg_kernel() {
    int i = blockIdx.x * blockDim.x + threadIdx.x;
    if (i < NUSERS) g_deg_u[i] = 0;
    if (i < NITEMS) g_deg_i[i] = 0;
}

__global__ void __launch_bounds__(256) count_deg_kernel(
    const int* __restrict__ uidx, const int* __restrict__ iidx, int E) {
    int e = blockIdx.x * blockDim.x + threadIdx.x;
    if (e >= E) return;
    atomicAdd(&g_deg_u[uidx[e]], 1);
    atomicAdd(&g_deg_i[iidx[e]], 1);
}

__global__ void __launch_bounds__(256) norm_kernel(
    const int* __restrict__ uidx, const int* __restrict__ iidx, int E) {
    int e = blockIdx.x * blockDim.x + threadIdx.x;
    if (e >= E) return;
    int du = g_deg_u[uidx[e]]; if (du < 1) du = 1;
    int di = g_deg_i[iidx[e]]; if (di < 1) di = 1;
    g_norm[e] = rsqrtf((float)du * (float)di);
}

// acc(out) = table; cur_a = table; cur_b = 0
__global__ void __launch_bounds__(256) init_emb_kernel(
    const float4* __restrict__ ut, const float4* __restrict__ itb, float4* out) {
    int i = blockIdx.x * blockDim.x + threadIdx.x;
    if (i < NU4) {
        float4 v = ut[i];
        out[i] = v;
        ((float4*)g_ua)[i] = v;
        ((float4*)g_ub)[i] = make_float4(0.f, 0.f, 0.f, 0.f);
    } else if (i < NT4) {
        int j = i - NU4;
        float4 v = itb[j];
        out[i] = v;
        ((float4*)g_ia)[j] = v;
        ((float4*)g_ib)[j] = make_float4(0.f, 0.f, 0.f, 0.f);
    }
}

// One thread per (edge, 16B chunk). Fuses both directions (item->user and
// user->item) so the idx/norm loads are shared (L1 broadcast within warp).
__global__ void __launch_bounds__(256) prop_kernel(
    const int* __restrict__ uidx, const int* __restrict__ iidx, int E,
    const int* __restrict__ nl, int layer, int flip) {
    if (layer >= *nl) return;
    int t = blockIdx.x * blockDim.x + threadIdx.x;
    if (t >= E * 16) return;
    int e = t >> 4;
    int c = t & 15;

    const float4* su; const float4* si; float* du; float* di;
    if (!flip) { su = (const float4*)g_ua; si = (const float4*)g_ia; du = g_ub; di = g_ib; }
    else       { su = (const float4*)g_ub; si = (const float4*)g_ib; du = g_ua; di = g_ia; }

    int u  = uidx[e];
    int it = iidx[e];
    float w = g_norm[e];

    float4 vu = su[u  * 16 + c];   // user row chunk
    float4 vi = si[it * 16 + c];   // item row chunk

    red_add_v4(du + u  * EMB_D + c * 4,
               make_float4(w * vi.x, w * vi.y, w * vi.z, w * vi.w));
    red_add_v4(di + it * EMB_D + c * 4,
               make_float4(w * vu.x, w * vu.y, w * vu.z, w * vu.w));
}

// acc += this layer's output (D); zero the source buffer (S), which becomes
// next layer's destination.
__global__ void __launch_bounds__(256) finish_kernel(
    float4* out, const int* __restrict__ nl, int layer, int flip) {
    if (layer >= *nl) return;
    int i = blockIdx.x * blockDim.x + threadIdx.x;
    if (i >= NT4) return;

    float4 *Du, *Di, *Su, *Si;
    if (!flip) { Du = (float4*)g_ub; Di = (float4*)g_ib; Su = (float4*)g_ua; Si = (float4*)g_ia; }
    else       { Du = (float4*)g_ua; Di = (float4*)g_ia; Su = (float4*)g_ub; Si = (float4*)g_ib; }

    float4 z = make_float4(0.f, 0.f, 0.f, 0.f);
    if (i < NU4) {
        float4 a = out[i], d = Du[i];
        out[i] = make_float4(a.x + d.x, a.y + d.y, a.z + d.z, a.w + d.w);
        Su[i] = z;
    } else {
        int j = i - NU4;
        float4 a = out[i], d = Di[j];
        out[i] = make_float4(a.x + d.x, a.y + d.y, a.z + d.z, a.w + d.w);
        Si[j] = z;
    }
}

__global__ void __launch_bounds__(256) scale_kernel(
    float4* out, const int* __restrict__ nl) {
    int i = blockIdx.x * blockDim.x + threadIdx.x;
    if (i >= NT4) return;
    float s = 1.0f / (float)(*nl + 1);
    float4 v = out[i];
    out[i] = make_float4(v.x * s, v.y * s, v.z * s, v.w * s);
}

// ---------------------------------------------------------------------------
extern "C" void kernel_launch(void* const* d_in, const int* in_sizes, int n_in,
                              void* d_out, int out_size) {
    const float* ut  = (const float*)d_in[0];
    const float* itb = (const float*)d_in[1];
    const int* uidx  = (const int*)d_in[2];
    const int* iidx  = (const int*)d_in[3];
    const int* nl    = (const int*)d_in[4];
    float* out = (float*)d_out;

    int E = in_sizes[2];
    if (E > MAXE) E = MAXE;

    const int T = 256;
    int deg_blocks  = (NUSERS + T - 1) / T;            // covers items too (NITEMS < NUSERS)
    int edge_blocks = (E + T - 1) / T;
    int emb_blocks  = (NT4 + T - 1) / T;
    int prop_blocks = (E * 16 + T - 1) / T;

    zero_deg_kernel<<<deg_blocks, T>>>();
    count_deg_kernel<<<edge_blocks, T>>>(uidx, iidx, E);
    norm_kernel<<<edge_blocks, T>>>(uidx, iidx, E);
    init_emb_kernel<<<emb_blocks, T>>>((const float4*)ut, (const float4*)itb,
                                       (float4*)out);

    for (int l = 0; l < MAX_LAYERS; l++) {
        int flip = l & 1;  // layer 0: read A, write B
        prop_kernel<<<prop_blocks, T>>>(uidx, iidx, E, nl, l, flip);
        finish_kernel<<<emb_blocks, T>>>((float4*)out, nl, l, flip);
    }

    scale_kernel<<<emb_blocks, T>>>((float4*)out, nl);
}

// round 9
// speedup vs baseline: 1.5904x; 1.5904x over previous
#include <cuda_runtime.h>
#include <cuda_bf16.h>

// FastMMGCN: LightGCN 3-layer propagation, pull-based CSR formulation.
//
// Inputs (metadata order):
//   d_in[0] user_table  f32 [100000, 64]
//   d_in[1] item_table  f32 [50000, 64]
//   d_in[2] user_idx    i32 [2000000]
//   d_in[3] item_idx    i32 [2000000]
//   d_in[4] num_layers  i32 scalar (device-resident)
// Output: f32 [150000, 64] = concat(acc_u, acc_i) / (num_layers+1)
//
// NOTE: __device__ globals must NEVER be passed as kernel arguments from host
// code (host shadow address != device address; on GB300 ATS makes it silently
// readable -> garbage, the R2 bug). All globals are referenced in device code.

#define NUSERS 100000
#define NITEMS 50000
#define NTOT   (NUSERS + NITEMS)
#define MAXE   2000000
#define EMB_D  64
#define MAX_LAYERS 4

#define NU4 (NUSERS * EMB_D / 4)
#define NI4 (NITEMS * EMB_D / 4)
#define NT4 (NU4 + NI4)

// ---- static device scratch (no allocation allowed) ----
__device__ int       g_deg_u[NUSERS];
__device__ int       g_deg_i[NITEMS];
__device__ int       g_offs_u[NUSERS + 1];
__device__ int       g_offs_i[NITEMS + 1];
__device__ int       g_cur_u[NUSERS];
__device__ int       g_cur_i[NITEMS];
__device__ int       g_part_u[128];
__device__ int       g_part_i[128];
__device__ float     g_norm[MAXE];
__device__ long long g_ent_u[MAXE];   // packed {norm(f32)<<32 | item_idx}
__device__ long long g_ent_i[MAXE];   // packed {norm(f32)<<32 | user_idx}
__device__ float4    g_ua[NU4];       // user cur ping (float4 => 16B aligned)
__device__ float4    g_ub[NU4];       // user cur pong
__device__ float4    g_ia[NI4];
__device__ float4    g_ib[NI4];

__device__ __forceinline__ long long pack_ent(int s, float w) {
    return ((long long)__float_as_int(w) << 32) | (unsigned int)s;
}

// ---------------------------------------------------------------------------
__global__ void __launch_bounds__(256) zero_deg_kernel() {
    int i = blockIdx.x * blockDim.x + threadIdx.x;
    if (i < NUSERS) g_deg_u[i] = 0;
    if (i < NITEMS) g_deg_i[i] = 0;
}

__global__ void __launch_bounds__(256) count_deg_kernel(
    const int* __restrict__ uidx, const int* __restrict__ iidx, int E) {
    int e = blockIdx.x * blockDim.x + threadIdx.x;
    if (e >= E) return;
    atomicAdd(&g_deg_u[uidx[e]], 1);
    atomicAdd(&g_deg_i[iidx[e]], 1);
}

__global__ void __launch_bounds__(256) norm_kernel(
    const int* __restrict__ uidx, const int* __restrict__ iidx, int E) {
    int e = blockIdx.x * blockDim.x + threadIdx.x;
    if (e >= E) return;
    int du = g_deg_u[uidx[e]]; if (du < 1) du = 1;
    int di = g_deg_i[iidx[e]]; if (di < 1) di = 1;
    g_norm[e] = rsqrtf((float)du * (float)di);
}

// ---- exclusive scan (3-phase); which: 0 = user arrays, 1 = item arrays ----
__global__ void __launch_bounds__(1024) scan1_kernel(int which) {
    const int* __restrict__ deg = which ? g_deg_i : g_deg_u;
    int*  offs = which ? g_offs_i : g_offs_u;
    int*  part = which ? g_part_i : g_part_u;
    int   n    = which ? NITEMS   : NUSERS;

    __shared__ int sh[1024];
    int tid = threadIdx.x;
    int i = blockIdx.x * 1024 + tid;
    int v = (i < n) ? deg[i] : 0;
    sh[tid] = v;
    __syncthreads();
    for (int s = 1; s < 1024; s <<= 1) {
        int t = (tid >= s) ? sh[tid - s] : 0;
        __syncthreads();
        sh[tid] += t;
        __syncthreads();
    }
    if (i < n) offs[i] = sh[tid] - v;             // block-local exclusive
    if (tid == 1023) part[blockIdx.x] = sh[tid];  // block total
}

__global__ void __launch_bounds__(1024) scan2_kernel(int which, int nb) {
    int* part = which ? g_part_i : g_part_u;
    int* offs = which ? g_offs_i : g_offs_u;
    int  n    = which ? NITEMS   : NUSERS;

    __shared__ int sh[1024];
    int tid = threadIdx.x;
    int v = (tid < nb) ? part[tid] : 0;
    sh[tid] = v;
    __syncthreads();
    for (int s = 1; s < 1024; s <<= 1) {
        int t = (tid >= s) ? sh[tid - s] : 0;
        __syncthreads();
        sh[tid] += t;
        __syncthreads();
    }
    if (tid < nb) part[tid] = sh[tid] - v;   // exclusive block prefix
    if (tid == 1023) offs[n] = sh[1023];     // grand total
}

__global__ void __launch_bounds__(1024) scan3_kernel(int which) {
    const int* __restrict__ part = which ? g_part_i : g_part_u;
    int* offs = which ? g_offs_i : g_offs_u;
    int  n    = which ? NITEMS   : NUSERS;
    int i = blockIdx.x * 1024 + threadIdx.x;
    if (i < n) offs[i] += part[blockIdx.x];
}

__global__ void __launch_bounds__(256) cursor_init_kernel() {
    int i = blockIdx.x * blockDim.x + threadIdx.x;
    if (i < NUSERS) g_cur_u[i] = g_offs_u[i];
    if (i < NITEMS) g_cur_i[i] = g_offs_i[i];
}

__global__ void __launch_bounds__(256) scatter_csr_kernel(
    const int* __restrict__ uidx, const int* __restrict__ iidx, int E) {
    int e = blockIdx.x * blockDim.x + threadIdx.x;
    if (e >= E) return;
    int u = uidx[e], it = iidx[e];
    float w = g_norm[e];
    int pu = atomicAdd(&g_cur_u[u], 1);
    g_ent_u[pu] = pack_ent(it, w);
    int pi = atomicAdd(&g_cur_i[it], 1);
    g_ent_i[pi] = pack_ent(u, w);
}

// out = table; cur ping = table (pong fully overwritten by layer 0)
__global__ void __launch_bounds__(256) init_emb_kernel(
    const float4* __restrict__ ut, const float4* __restrict__ itb,
    float4* __restrict__ out) {
    int i = blockIdx.x * blockDim.x + threadIdx.x;
    if (i < NU4) {
        float4 v = ut[i];
        out[i] = v;
        g_ua[i] = v;
    } else if (i < NT4) {
        int j = i - NU4;
        float4 v = itb[j];
        out[i] = v;
        g_ia[j] = v;
    }
}

// One warp per destination node; lane owns 2 floats of the 64-wide row.
// Pull-aggregate: next[node] = sum_e w_e * src[neighbor_e]; out[node] += next.
__global__ void __launch_bounds__(256) pull_kernel(
    const int* __restrict__ nl, int layer, int flip, float* __restrict__ out) {
    if (layer >= *nl) return;
    int gw   = (blockIdx.x * blockDim.x + threadIdx.x) >> 5;
    int lane = threadIdx.x & 31;
    if (gw >= NTOT) return;

    const float* __restrict__ src;
    float* nxt;
    const long long* __restrict__ ent;
    int beg, end;
    if (gw < NUSERS) {
        src = (const float*)(flip ? g_ib : g_ia);       // read item cur
        nxt = (float*)(flip ? g_ua : g_ub) + gw * EMB_D;
        ent = g_ent_u;
        beg = g_offs_u[gw];
        end = g_offs_u[gw + 1];
    } else {
        int it = gw - NUSERS;
        src = (const float*)(flip ? g_ub : g_ua);       // read user cur
        nxt = (float*)(flip ? g_ia : g_ib) + it * EMB_D;
        ent = g_ent_i;
        beg = g_offs_i[it];
        end = g_offs_i[it + 1];
    }
    float* orow = out + (long)gw * EMB_D;               // concat layout == gw

    float accx = 0.f, accy = 0.f;
    for (int base = beg; base < end; base += 32) {
        int idx = base + lane;
        long long mine = (idx < end) ? ent[idx] : 0;
        int cnt = end - base; if (cnt > 32) cnt = 32;
        #pragma unroll 4
        for (int j = 0; j < cnt; j++) {
            long long e = __shfl_sync(0xffffffffu, mine, j);
            int   s = (int)(e & 0xffffffffLL);
            float w = __int_as_float((int)(e >> 32));
            float2 v = *reinterpret_cast<const float2*>(src + s * EMB_D + lane * 2);
            accx = fmaf(w, v.x, accx);
            accy = fmaf(w, v.y, accy);
        }
    }

    *reinterpret_cast<float2*>(nxt + lane * 2) = make_float2(accx, accy);
    float2* op = reinterpret_cast<float2*>(orow + lane * 2);
    float2 o = *op;
    o.x += accx; o.y += accy;
    *op = o;
}

__global__ void __launch_bounds__(256) scale_kernel(
    float4* __restrict__ out, const int* __restrict__ nl) {
    int i = blockIdx.x * blockDim.x + threadIdx.x;
    if (i >= NT4) return;
    float s = 1.0f / (float)(*nl + 1);
    float4 v = out[i];
    out[i] = make_float4(v.x * s, v.y * s, v.z * s, v.w * s);
}

// ---------------------------------------------------------------------------
extern "C" void kernel_launch(void* const* d_in, const int* in_sizes, int n_in,
                              void* d_out, int out_size) {
    const float* ut  = (const float*)d_in[0];
    const float* itb = (const float*)d_in[1];
    const int* uidx  = (const int*)d_in[2];
    const int* iidx  = (const int*)d_in[3];
    const int* nl    = (const int*)d_in[4];
    float* out = (float*)d_out;

    int E = in_sizes[2];
    if (E > MAXE) E = MAXE;

    const int T = 256;
    int deg_blocks  = (NUSERS + T - 1) / T;
    int edge_blocks = (E + T - 1) / T;
    int emb_blocks  = (NT4 + T - 1) / T;
    int pull_blocks = (NTOT * 32 + T - 1) / T;
    int ub = (NUSERS + 1023) / 1024;   // 98
    int ib = (NITEMS + 1023) / 1024;   // 49

    // degrees + per-edge norm
    zero_deg_kernel<<<deg_blocks, T>>>();
    count_deg_kernel<<<edge_blocks, T>>>(uidx, iidx, E);
    norm_kernel<<<edge_blocks, T>>>(uidx, iidx, E);

    // CSR build (both directions); globals selected inside device code
    scan1_kernel<<<ub, 1024>>>(0);
    scan1_kernel<<<ib, 1024>>>(1);
    scan2_kernel<<<1, 1024>>>(0, ub);
    scan2_kernel<<<1, 1024>>>(1, ib);
    scan3_kernel<<<ub, 1024>>>(0);
    scan3_kernel<<<ib, 1024>>>(1);
    cursor_init_kernel<<<deg_blocks, T>>>();
    scatter_csr_kernel<<<edge_blocks, T>>>(uidx, iidx, E);

    // embeddings
    init_emb_kernel<<<emb_blocks, T>>>((const float4*)ut, (const float4*)itb,
                                       (float4*)out);

    for (int l = 0; l < MAX_LAYERS; l++) {
        pull_kernel<<<pull_blocks, T>>>(nl, l, l & 1, out);
    }

    scale_kernel<<<emb_blocks, T>>>((float4*)out, nl);
}